// round 15
// baseline (speedup 1.0000x reference)
#include <cuda_runtime.h>
#include <math.h>
#include <stdint.h>

#define BB 4
#define LL 2048
#define LQ 1024
#define DM 512
#define DIN 1024
#define DSTATE 64
#define NH 16
#define HD 64
#define DXBC 1152
#define ZXW 2176      // z + xBC columns kept in g_zx (row stride)
#define WIN_LD 2192   // full in_proj width (z + xBC + dt)
#define CQ 64         // chunk length
#define NCH (LL/CQ)   // 32 chunks per sequence
#define NCHH (2*BB*NH*NCH)   // 4096 chunk-heads

// ---------------- scratch (device globals; allocation-free) ----------------
__device__ float g_u[2][BB*LL*DM];        // rmsnormed inputs (fp32, for dt path)
__device__ float g_u32[2][BB*LL*DM];      // rmsnormed inputs (tf32-rounded, GEMM A)
__device__ float g_zx[2][BB*LL*ZXW];      // in_proj outputs (z + xBC)
__device__ float g_xbc[2][BB*LL*DXBC];    // conv+silu outputs
__device__ float g_dtT[2][NH*BB*LL];      // dt transposed [h][row]
__device__ float g_laT[2][NH*BB*LL];      // log-decay la = -exp(Alog)*dt, [h][row]
__device__ float g_S[NCHH*64*64];         // chunk state contributions [ch][p*64+n]
__device__ float g_h[NCHH*64*64];         // h state entering each chunk
__device__ float g_lc[NCHH*CQ];           // in-chunk inclusive log-decay prefix
__device__ float g_y[2][BB*LL*DIN];       // scan outputs (+D*x)
__device__ float g_nrm[2][BB*LQ*DIN];     // gated rmsnorm (tf32-rounded)
__device__ float g_fs[BB*LQ*DM];          // factual pre-out-proj (tf32-rounded)
__device__ float g_win32[2][DM*ZXW];      // tf32 weights
__device__ float g_wout32[2][DIN*DM];
__device__ float g_wo32[DM*DM];

// ---------------- helpers ----------------
__device__ __forceinline__ float silu(float x) { return x / (1.f + expf(-x)); }

__device__ __forceinline__ uint32_t f2tf32(float x) {
    uint32_t r;
    asm("cvt.rna.tf32.f32 %0, %1;" : "=r"(r) : "f"(x));
    return r;
}
__device__ __forceinline__ float tf32r(float x) { return __uint_as_float(f2tf32(x)); }

__device__ __forceinline__ void mma_tf32(float* c, const uint32_t* a, const uint32_t* b) {
    asm volatile("mma.sync.aligned.m16n8k8.row.col.f32.tf32.tf32.f32 "
        "{%0,%1,%2,%3}, {%4,%5,%6,%7}, {%8,%9}, {%0,%1,%2,%3};"
        : "+f"(c[0]), "+f"(c[1]), "+f"(c[2]), "+f"(c[3])
        : "r"(a[0]), "r"(a[1]), "r"(a[2]), "r"(a[3]), "r"(b[0]), "r"(b[1]));
}

__device__ __forceinline__ void cpa16(float* dst, const float* src) {
    uint32_t d = (uint32_t)__cvta_generic_to_shared(dst);
    asm volatile("cp.async.cg.shared.global [%0], [%1], 16;" :: "r"(d), "l"(src));
}
__device__ __forceinline__ void cpa_commit() { asm volatile("cp.async.commit_group;"); }
template<int N> __device__ __forceinline__ void cpa_wait() {
    asm volatile("cp.async.wait_group %0;" :: "n"(N));
}

// ---------------- launch 0: input rmsnorm + weight cvt (fused) -------------
#define CVT_TOT (2*DM*ZXW + 2*DIN*DM + DM*DM)
__global__ void __launch_bounds__(128) prep_cvt(
    const float* __restrict__ q, const float* __restrict__ kv,
    const float* __restrict__ fw, const float* __restrict__ cw,
    const float* __restrict__ fWin, const float* __restrict__ cWin,
    const float* __restrict__ fWout, const float* __restrict__ cWout,
    const float* __restrict__ oW)
{
    int t = threadIdx.x;
    if (blockIdx.y == 1) {
        for (int i = blockIdx.x * 128 + t; i < CVT_TOT; i += 16384 * 128) {
            int j = i;
            if (j < 2 * DM * ZXW) {
                int reg = j / (DM * ZXW);
                int k = j - reg * (DM * ZXW);
                const float* s = reg ? cWin : fWin;
                int r = k / ZXW, c = k - r * ZXW;
                g_win32[reg][k] = tf32r(s[r * WIN_LD + c]);
            } else if ((j -= 2 * DM * ZXW) < 2 * DIN * DM) {
                int reg = j / (DIN * DM);
                int k = j - reg * (DIN * DM);
                g_wout32[reg][k] = tf32r((reg ? cWout : fWout)[k]);
            } else {
                j -= 2 * DIN * DM;
                g_wo32[j] = tf32r(oW[j]);
            }
        }
        return;
    }

    int row = blockIdx.x;            // 2 * 4 * 2048 rows
    int br  = row >> 13;
    int r   = row & 8191;
    int b   = r >> 11;
    int l   = r & 2047;
    const float* src;
    if (l < LQ) {
        int li = (br == 0) ? l : (LQ - 1 - l);
        src = kv + (b * LQ + li) * DM;
    } else {
        src = q + (b * LQ + (l - LQ)) * DM;
    }
    const float* w = br ? cw : fw;

    float v[4];
    float ss = 0.f;
#pragma unroll
    for (int i = 0; i < 4; i++) { v[i] = src[t + i * 128]; ss += v[i] * v[i]; }

    __shared__ float red[4];
#pragma unroll
    for (int o = 16; o > 0; o >>= 1) ss += __shfl_xor_sync(0xffffffffu, ss, o);
    if ((t & 31) == 0) red[t >> 5] = ss;
    __syncthreads();
    float total = red[0] + red[1] + red[2] + red[3];
    float scale = rsqrtf(total / (float)DM + 1e-5f);

    float* dst   = g_u[br]   + (b * LL + l) * DM;
    float* dst32 = g_u32[br] + (b * LL + l) * DM;
#pragma unroll
    for (int i = 0; i < 4; i++) {
        int idx = t + i * 128;
        float val = v[i] * scale * w[idx];
        dst[idx] = val;
        dst32[idx] = tf32r(val);
    }
}

// ---------------- TF32 GEMM: 128x128x32 tile, 8 warps, 2-stage buffer ------
#define AS_LD 36
#define BS_LD 136
#define A_STG (128 * AS_LD)
#define B_STG (32 * BS_LD)
#define B_OFF (2 * A_STG)
#define GEMM_SMEM ((2 * (A_STG + B_STG)) * 4)   // 71680 B -> 3 CTAs/SM

__global__ void __launch_bounds__(256) gemm_tf32(
    const float* __restrict__ A0, const float* __restrict__ A1,
    const float* __restrict__ B0, const float* __restrict__ B1,
    float* __restrict__ C0, float* __restrict__ C1,
    const float* __restrict__ bias,
    int M, int N, int K, int lda, int ldb, int ldc, int roundMask)
{
    extern __shared__ float sm[];
    int z = blockIdx.z;
    const float* A = z ? A1 : A0;
    const float* B = z ? B1 : B0;
    float* C = z ? C1 : C0;
    bool rnd = (roundMask >> z) & 1;

    int tid = threadIdx.x;
    int bm = blockIdx.y * 128, bn = blockIdx.x * 128;

    int w = tid >> 5;
    int lane = tid & 31;
    int g = lane >> 2, cq = lane & 3;
    int mw = (w & 1) * 64;
    int nw = (w >> 1) * 32;

    int a_r = tid >> 3, a_c4 = (tid & 7) * 4;
    int b_r = tid >> 5, b_c4 = (tid & 31) * 4;

    const float* Ag = A + (bm + a_r) * lda + a_c4;
    const float* Bg = B + b_r * ldb + bn + b_c4;

    int nk = K >> 5;

    // prologue: load stage 0
    {
        float* As = sm;
        float* Bs = sm + B_OFF;
#pragma unroll
        for (int rr = 0; rr < 4; rr++)
            cpa16(&As[(a_r + rr * 32) * AS_LD + a_c4], Ag + rr * 32 * lda);
#pragma unroll
        for (int rr = 0; rr < 4; rr++)
            cpa16(&Bs[(b_r + rr * 8) * BS_LD + b_c4], Bg + (rr * 8) * ldb);
        cpa_commit();
    }

    float acc[4][4][4];
#pragma unroll
    for (int i = 0; i < 4; i++)
#pragma unroll
        for (int j = 0; j < 4; j++)
#pragma unroll
            for (int x = 0; x < 4; x++) acc[i][j][x] = 0.f;

    for (int kt = 0; kt < nk; kt++) {
        // issue next tile's loads into the other buffer (overlaps this compute)
        if (kt + 1 < nk) {
            int st = (kt + 1) & 1;
            float* As = sm + st * A_STG;
            float* Bs = sm + B_OFF + st * B_STG;
            int k0 = (kt + 1) * 32;
#pragma unroll
            for (int rr = 0; rr < 4; rr++)
                cpa16(&As[(a_r + rr * 32) * AS_LD + a_c4], Ag + rr * 32 * lda + k0);
#pragma unroll
            for (int rr = 0; rr < 4; rr++)
                cpa16(&Bs[(b_r + rr * 8) * BS_LD + b_c4], Bg + (k0 + rr * 8) * ldb);
            cpa_commit();
            cpa_wait<1>();    // kt's data complete (kt+1 group may remain)
        } else {
            cpa_wait<0>();
        }
        __syncthreads();

        const float* As = sm + (kt & 1) * A_STG;
        const float* Bs = sm + B_OFF + (kt & 1) * B_STG;
#pragma unroll
        for (int ks = 0; ks < 4; ks++) {
            int k0 = ks * 8;
            uint32_t af[4][4], bf[4][2];
#pragma unroll
            for (int i = 0; i < 4; i++) {
                int m = mw + i * 16 + g;
                af[i][0] = __float_as_uint(As[m * AS_LD + k0 + cq]);
                af[i][1] = __float_as_uint(As[(m + 8) * AS_LD + k0 + cq]);
                af[i][2] = __float_as_uint(As[m * AS_LD + k0 + cq + 4]);
                af[i][3] = __float_as_uint(As[(m + 8) * AS_LD + k0 + cq + 4]);
            }
#pragma unroll
            for (int j = 0; j < 4; j++) {
                int n = nw + j * 8 + g;
                bf[j][0] = __float_as_uint(Bs[(k0 + cq) * BS_LD + n]);
                bf[j][1] = __float_as_uint(Bs[(k0 + cq + 4) * BS_LD + n]);
            }
#pragma unroll
            for (int i = 0; i < 4; i++)
#pragma unroll
                for (int j = 0; j < 4; j++)
                    mma_tf32(acc[i][j], af[i], bf[j]);
        }
        __syncthreads();   // protect buffer (kt+1)'s target from early overwrite
    }

#pragma unroll
    for (int i = 0; i < 4; i++) {
        int m0 = bm + mw + i * 16 + g;
#pragma unroll
        for (int j = 0; j < 4; j++) {
            int n = bn + nw + j * 8 + 2 * cq;
            float b0 = 0.f, b1 = 0.f;
            if (bias) { b0 = bias[n]; b1 = bias[n + 1]; }
            float v00 = acc[i][j][0] + b0, v01 = acc[i][j][1] + b1;
            float v10 = acc[i][j][2] + b0, v11 = acc[i][j][3] + b1;
            if (rnd) { v00 = tf32r(v00); v01 = tf32r(v01); v10 = tf32r(v10); v11 = tf32r(v11); }
            float2 lo = { v00, v01 }, hi = { v10, v11 };
            *(float2*)&C[m0 * ldc + n] = lo;
            *(float2*)&C[(m0 + 8) * ldc + n] = hi;
        }
    }
}

// ---------------- launch 2: conv+silu AND dt-gemm (fused) ------------------
__global__ void __launch_bounds__(288) conv_dt(
    const float* __restrict__ fw, const float* __restrict__ fb,
    const float* __restrict__ cw_, const float* __restrict__ cb,
    const float* __restrict__ fWin, const float* __restrict__ cWin,
    const float* __restrict__ fdtb, const float* __restrict__ cdtb,
    const float* __restrict__ fAl,  const float* __restrict__ cAl)
{
    int br = blockIdx.y;
    int tid = threadIdx.x;

    if (blockIdx.x < BB * LL) {
        const float* w = br ? cw_ : fw;
        const float* bias = br ? cb : fb;
        int row = blockIdx.x;
        int b = row >> 11;
        int l = row & 2047;
        int c4 = tid * 4;

        float4 w0 = *(const float4*)(w + c4 * 4);
        float4 w1 = *(const float4*)(w + c4 * 4 + 4);
        float4 w2 = *(const float4*)(w + c4 * 4 + 8);
        float4 w3 = *(const float4*)(w + c4 * 4 + 12);
        float4 acc = *(const float4*)(bias + c4);

        const float* zbase = g_zx[br] + (size_t)(b * LL) * ZXW + DIN + c4;
#pragma unroll
        for (int j = 0; j < 4; j++) {
            int ls = l - 3 + j;
            if (ls >= 0) {
                float4 x = *(const float4*)(zbase + (size_t)ls * ZXW);
                acc.x += x.x * ((const float*)&w0)[j];
                acc.y += x.y * ((const float*)&w1)[j];
                acc.z += x.z * ((const float*)&w2)[j];
                acc.w += x.w * ((const float*)&w3)[j];
            }
        }
        float4 outv = { silu(acc.x), silu(acc.y), silu(acc.z), silu(acc.w) };
        *(float4*)(g_xbc[br] + (size_t)blockIdx.x * DXBC + c4) = outv;
        return;
    }

    const float* Win = br ? cWin : fWin;
    const float* dtb = br ? cdtb : fdtb;
    const float* Alog = br ? cAl : fAl;
    const float* u = g_u[br];

    __shared__ float Ws[512][16];
    for (int i = tid; i < 512 * 16; i += 288) {
        int k = i >> 4, h = i & 15;
        Ws[k][h] = Win[k * WIN_LD + ZXW + h];
    }
    __syncthreads();
    if (tid >= 256) return;

    int rib = tid >> 4;
    int h   = tid & 15;
    int row = (blockIdx.x - BB * LL) * 16 + rib;
    const float* arow = u + row * DM;

    float a0 = 0.f, a1 = 0.f, a2 = 0.f, a3 = 0.f;
#pragma unroll 4
    for (int k = 0; k < 512; k += 4) {
        a0 += arow[k]     * Ws[k][h];
        a1 += arow[k + 1] * Ws[k + 1][h];
        a2 += arow[k + 2] * Ws[k + 2][h];
        a3 += arow[k + 3] * Ws[k + 3][h];
    }
    float acc = dtb[h] + ((a0 + a1) + (a2 + a3));

    float dt = acc > 20.f ? acc : log1pf(expf(acc));
    g_dtT[br][h * (BB * LL) + row] = dt;
    g_laT[br][h * (BB * LL) + row] = -expf(Alog[h]) * dt;
}

// ---------------- launch 3: chunk state contributions (Phase A) ------------
__global__ void __launch_bounds__(128) chunk_state()
{
    int ch = blockIdx.x;             // 4096
    int c  = ch & 31;
    int h  = (ch >> 5) & 15;
    int b  = (ch >> 9) & 3;
    int br = ch >> 11;

    const float* xbc = g_xbc[br];
    const float* dtp = g_dtT[br] + h * (BB * LL);
    const float* lap = g_laT[br] + h * (BB * LL);
    int rowbase = b * LL + c * CQ;

    __shared__ float Xs[CQ * 64];
    __shared__ float Bw[CQ * 64];
    __shared__ float lc[CQ];
    __shared__ float wgt[CQ];

    int tid = threadIdx.x;

    if (tid < CQ) lc[tid] = lap[rowbase + tid];
    __syncthreads();
    for (int off = 1; off < CQ; off <<= 1) {
        float v = 0.f;
        if (tid < CQ && tid >= off) v = lc[tid - off];
        __syncthreads();
        if (tid < CQ) lc[tid] += v;
        __syncthreads();
    }
    if (tid < CQ) {
        wgt[tid] = dtp[rowbase + tid] * __expf(lc[CQ - 1] - lc[tid]);
        g_lc[ch * CQ + tid] = lc[tid];
    }

    for (int k = tid; k < CQ * 16; k += 128) {
        int s = k >> 4, q = (k & 15) * 4;
        size_t off = (size_t)(rowbase + s) * DXBC;
        *(float4*)&Xs[s * 64 + q] = *(const float4*)(xbc + off + h * 64 + q);
        *(float4*)&Bw[s * 64 + q] = *(const float4*)(xbc + off + 1024 + q);
    }
    __syncthreads();
    for (int k = tid; k < CQ * 16; k += 128) {
        int s = k >> 4, q = (k & 15) * 4;
        float ws = wgt[s];
        float4 v = *(float4*)&Bw[s * 64 + q];
        v.x *= ws; v.y *= ws; v.z *= ws; v.w *= ws;
        *(float4*)&Bw[s * 64 + q] = v;
    }
    __syncthreads();

    int p0 = (tid >> 3) * 4, n0 = (tid & 7) * 8;
    float acc[4][8];
#pragma unroll
    for (int i = 0; i < 4; i++)
#pragma unroll
        for (int j = 0; j < 8; j++) acc[i][j] = 0.f;

    for (int s = 0; s < CQ; s++) {
        float4 xv = *(const float4*)&Xs[s * 64 + p0];
        float4 b0 = *(const float4*)&Bw[s * 64 + n0];
        float4 b1 = *(const float4*)&Bw[s * 64 + n0 + 4];
        const float* xf = (const float*)&xv;
#pragma unroll
        for (int i = 0; i < 4; i++) {
            float x = xf[i];
            acc[i][0] += x * b0.x; acc[i][1] += x * b0.y;
            acc[i][2] += x * b0.z; acc[i][3] += x * b0.w;
            acc[i][4] += x * b1.x; acc[i][5] += x * b1.y;
            acc[i][6] += x * b1.z; acc[i][7] += x * b1.w;
        }
    }

    float* Sp = g_S + (size_t)ch * 4096;
#pragma unroll
    for (int i = 0; i < 4; i++) {
        *(float4*)&Sp[(p0 + i) * 64 + n0]     = *(float4*)&acc[i][0];
        *(float4*)&Sp[(p0 + i) * 64 + n0 + 4] = *(float4*)&acc[i][4];
    }
}

// ---------------- launch 4: inter-chunk state scan (Phase B) ---------------
__global__ void __launch_bounds__(1024) state_scan()
{
    int sh = blockIdx.x;
    int tid = threadIdx.x;
    size_t base = (size_t)sh * NCH * 4096 + tid * 4;

    float4 hr = make_float4(0.f, 0.f, 0.f, 0.f);

    for (int c = 0; c < NCH; c++) {
        size_t off = base + (size_t)c * 4096;
        *(float4*)(g_h + off) = hr;
        float Aend = __expf(g_lc[(sh * NCH + c) * CQ + CQ - 1]);
        float4 s = *(const float4*)(g_S + off);
        hr.x = hr.x * Aend + s.x;
        hr.y = hr.y * Aend + s.y;
        hr.z = hr.z * Aend + s.z;
        hr.w = hr.w * Aend + s.w;
    }
}

// ---------------- launch 5: chunk outputs (Phase C, 256 threads) -----------
#define CO_PAD 65
#define CO_ARR (CQ * CO_PAD)
#define CO_SMEM ((4 * CO_ARR + 3 * CQ) * 4)
__global__ void __launch_bounds__(256) chunk_out(const float* __restrict__ fD,
                                                 const float* __restrict__ cD)
{
    extern __shared__ float smc[];
    float* Cs = smc;
    float* XB = smc + CO_ARR;
    float* G  = smc + 2 * CO_ARR;
    float* Hs = smc + 3 * CO_ARR;
    float* lc = smc + 4 * CO_ARR;
    float* dts = lc + CQ;
    float* elc = dts + CQ;

    int ch = blockIdx.x;
    int c  = ch & 31;
    int h  = (ch >> 5) & 15;
    int b  = (ch >> 9) & 3;
    int br = ch >> 11;

    const float* xbc = g_xbc[br];
    const float* dtp = g_dtT[br] + h * (BB * LL);
    float Dh = (br ? cD : fD)[h];
    int rowbase = b * LL + c * CQ;
    int tid = threadIdx.x;

    if (tid < CQ) {
        float l = g_lc[ch * CQ + tid];
        lc[tid] = l;
        elc[tid] = __expf(l);
        dts[tid] = dtp[rowbase + tid];
    }

    // load C, B (into XB), h_prev — gmem float4, scalar STS (odd stride)
    for (int k = tid; k < CQ * 16; k += 256) {
        int s = k >> 4, q = (k & 15) * 4;
        size_t off = (size_t)(rowbase + s) * DXBC;
        float4 cv = *(const float4*)(xbc + off + 1088 + q);
        float4 bv = *(const float4*)(xbc + off + 1024 + q);
        float4 hv = *(const float4*)(g_h + (size_t)ch * 4096 + s * 64 + q);
        Cs[s * CO_PAD + q]     = cv.x; Cs[s * CO_PAD + q + 1] = cv.y;
        Cs[s * CO_PAD + q + 2] = cv.z; Cs[s * CO_PAD + q + 3] = cv.w;
        XB[s * CO_PAD + q]     = bv.x; XB[s * CO_PAD + q + 1] = bv.y;
        XB[s * CO_PAD + q + 2] = bv.z; XB[s * CO_PAD + q + 3] = bv.w;
        Hs[s * CO_PAD + q]     = hv.x; Hs[s * CO_PAD + q + 1] = hv.y;
        Hs[s * CO_PAD + q + 2] = hv.z; Hs[s * CO_PAD + q + 3] = hv.w;
    }
    __syncthreads();

    // G[t,s] = (C_t . B_s) masked-decayed; thread = 2t x 8s
    {
        int t0 = (tid >> 3) * 2, s0 = (tid & 7) * 8;
        float acc[2][8];
#pragma unroll
        for (int i = 0; i < 2; i++)
#pragma unroll
            for (int j = 0; j < 8; j++) acc[i][j] = 0.f;
        for (int n = 0; n < 64; n++) {
            float cv[2], bv[8];
#pragma unroll
            for (int i = 0; i < 2; i++) cv[i] = Cs[(t0 + i) * CO_PAD + n];
#pragma unroll
            for (int j = 0; j < 8; j++) bv[j] = XB[(s0 + j) * CO_PAD + n];
#pragma unroll
            for (int i = 0; i < 2; i++)
#pragma unroll
                for (int j = 0; j < 8; j++) acc[i][j] += cv[i] * bv[j];
        }
#pragma unroll
        for (int i = 0; i < 2; i++) {
            int t = t0 + i;
#pragma unroll
            for (int j = 0; j < 8; j++) {
                int s = s0 + j;
                float gv = 0.f;
                if (s <= t) gv = acc[i][j] * __expf(lc[t] - lc[s]) * dts[s];
                G[t * CO_PAD + s] = gv;
            }
        }
    }
    __syncthreads();

    // overwrite XB with X (head slice) — scalar STS
    for (int k = tid; k < CQ * 16; k += 256) {
        int s = k >> 4, q = (k & 15) * 4;
        size_t off = (size_t)(rowbase + s) * DXBC;
        float4 xv = *(const float4*)(xbc + off + h * 64 + q);
        XB[s * CO_PAD + q]     = xv.x; XB[s * CO_PAD + q + 1] = xv.y;
        XB[s * CO_PAD + q + 2] = xv.z; XB[s * CO_PAD + q + 3] = xv.w;
    }
    __syncthreads();

    // Y[t,p] = G@X + elc[t]*(C@h^T) + Dh*x; thread = 2t x 8p
    {
        int t0 = (tid >> 3) * 2, p0 = (tid & 7) * 8;
        float y1[2][8], y2[2][8];
#pragma unroll
        for (int i = 0; i < 2; i++)
#pragma unroll
            for (int j = 0; j < 8; j++) { y1[i][j] = 0.f; y2[i][j] = 0.f; }

        for (int s = 0; s < 64; s++) {
            float gv[2], xv[8];
#pragma unroll
            for (int i = 0; i < 2; i++) gv[i] = G[(t0 + i) * CO_PAD + s];
#pragma unroll
            for (int j = 0; j < 8; j++) xv[j] = XB[s * CO_PAD + p0 + j];
#pragma unroll
            for (int i = 0; i < 2; i++) {
                float g = gv[i];
#pragma unroll
                for (int j = 0; j < 8; j++) y1[i][j] += g * xv[j];
            }
        }
        for (int n = 0; n < 64; n++) {
            float cv[2], hv[8];
#pragma unroll
            for (int i = 0; i < 2; i++) cv[i] = Cs[(t0 + i) * CO_PAD + n];
#pragma unroll
            for (int j = 0; j < 8; j++) hv[j] = Hs[(p0 + j) * CO_PAD + n];
#pragma unroll
            for (int i = 0; i < 2; i++)
#pragma unroll
                for (int j = 0; j < 8; j++) y2[i][j] += cv[i] * hv[j];
        }

        float* yp = g_y[br];
#pragma unroll
        for (int i = 0; i < 2; i++) {
            int t = t0 + i;
            float e = elc[t];
            float o[8];
#pragma unroll
            for (int j = 0; j < 8; j++)
                o[j] = y1[i][j] + e * y2[i][j] + Dh * XB[t * CO_PAD + p0 + j];
            float* dst = yp + (size_t)(rowbase + t) * DIN + h * HD + p0;
            *(float4*)dst = *(float4*)&o[0];
            *(float4*)(dst + 4) = *(float4*)&o[4];
        }
    }
}

// ---------------- y*silu(z) + rmsnorm (last LQ tokens, tf32 out) -----------
__global__ void yz_norm(const float* __restrict__ fnw, const float* __restrict__ cnw)
{
    int row = blockIdx.x;            // 2 * 4 * 1024
    int br = row >> 12;
    int r = row & 4095;
    int b = r >> 10;
    int lq = r & 1023;
    int l = lq + LQ;
    const float* nw = br ? cnw : fnw;
    const float* yrow = g_y[br] + (b * LL + l) * DIN;
    const float* zrow = g_zx[br] + (b * LL + l) * ZXW;

    int t = threadIdx.x;             // 256
    float v[4];
    float ss = 0.f;
#pragma unroll
    for (int i = 0; i < 4; i++) {
        int idx = t + i * 256;
        float z = zrow[idx];
        float val = yrow[idx] * silu(z);
        v[i] = val;
        ss += val * val;
    }

    __shared__ float red[8];
#pragma unroll
    for (int o = 16; o > 0; o >>= 1) ss += __shfl_xor_sync(0xffffffffu, ss, o);
    if ((t & 31) == 0) red[t >> 5] = ss;
    __syncthreads();
    float total = 0.f;
#pragma unroll
    for (int i = 0; i < 8; i++) total += red[i];
    float scale = rsqrtf(total / (float)DIN + 1e-5f);

    float* dst = g_nrm[br] + ((b << 10) + lq) * DIN;
#pragma unroll
    for (int i = 0; i < 4; i++) {
        int idx = t + i * 256;
        dst[idx] = tf32r(v[i] * scale * nw[idx]);
    }
}

// ---------------- launch ----------------------------------------------------
extern "C" void kernel_launch(void* const* d_in, const int* in_sizes, int n_in,
                              void* d_out, int out_size)
{
    const float* query   = (const float*)d_in[0];
    const float* kv      = (const float*)d_in[1];
    const float* fnorm_w = (const float*)d_in[2];
    const float* cnorm_w = (const float*)d_in[3];
    const float* f_Win   = (const float*)d_in[4];
    const float* f_convw = (const float*)d_in[5];
    const float* f_convb = (const float*)d_in[6];
    const float* f_dtb   = (const float*)d_in[7];
    const float* f_Alog  = (const float*)d_in[8];
    const float* f_D     = (const float*)d_in[9];
    const float* f_normw = (const float*)d_in[10];
    const float* f_Wout  = (const float*)d_in[11];
    const float* c_Win   = (const float*)d_in[12];
    const float* c_convw = (const float*)d_in[13];
    const float* c_convb = (const float*)d_in[14];
    const float* c_dtb   = (const float*)d_in[15];
    const float* c_Alog  = (const float*)d_in[16];
    const float* c_D     = (const float*)d_in[17];
    const float* c_normw = (const float*)d_in[18];
    const float* c_Wout  = (const float*)d_in[19];
    const float* outp_w  = (const float*)d_in[20];
    const float* outp_b  = (const float*)d_in[21];
    float* out = (float*)d_out;

    float *uP32, *zxP, *nrmP, *fsP, *win32P, *wout32P, *wo32P;
    cudaGetSymbolAddress((void**)&uP32,   g_u32);
    cudaGetSymbolAddress((void**)&zxP,    g_zx);
    cudaGetSymbolAddress((void**)&nrmP,   g_nrm);
    cudaGetSymbolAddress((void**)&fsP,    g_fs);
    cudaGetSymbolAddress((void**)&win32P, g_win32);
    cudaGetSymbolAddress((void**)&wout32P,g_wout32);
    cudaGetSymbolAddress((void**)&wo32P,  g_wo32);

    cudaFuncSetAttribute(gemm_tf32, cudaFuncAttributeMaxDynamicSharedMemorySize, GEMM_SMEM);
    cudaFuncSetAttribute(chunk_out, cudaFuncAttributeMaxDynamicSharedMemorySize, CO_SMEM);

    float* u32_f = uP32;
    float* u32_c = uP32 + BB * LL * DM;
    float* zx_f = zxP;
    float* zx_c = zxP + BB * LL * ZXW;
    float* nrm_f = nrmP;
    float* nrm_c = nrmP + BB * LQ * DIN;
    float* win_f = win32P;
    float* win_c = win32P + DM * ZXW;
    float* wout_f = wout32P;
    float* wout_c = wout32P + DIN * DM;

    // (0) input rmsnorm + weight cvt (fused)
    {
        dim3 grid(2 * BB * LL, 2);
        prep_cvt<<<grid, 128>>>(query, kv, fnorm_w, cnorm_w,
                                f_Win, c_Win, f_Wout, c_Wout, outp_w);
    }

    // (1) in_proj GEMMs
    {
        dim3 grid(ZXW / 128, (BB * LL) / 128, 2);
        gemm_tf32<<<grid, 256, GEMM_SMEM>>>(u32_f, u32_c, win_f, win_c, zx_f, zx_c,
                                            nullptr, BB * LL, ZXW, DM, DM, ZXW, ZXW, 0);
    }

    // (2) conv+silu + dt/la (fused)
    {
        dim3 grid(BB * LL + (BB * LL) / 16, 2);
        conv_dt<<<grid, 288>>>(f_convw, f_convb, c_convw, c_convb,
                               f_Win, c_Win, f_dtb, c_dtb, f_Alog, c_Alog);
    }

    // (3) chunked SSD phase A: chunk states
    chunk_state<<<NCHH, 128>>>();

    // (4) phase B: inter-chunk state scan
    state_scan<<<2 * BB * NH, 1024>>>();

    // (5) phase C: chunk outputs (256 threads)
    chunk_out<<<NCHH, 256, CO_SMEM>>>(f_D, c_D);

    // (6) gate + rmsnorm
    yz_norm<<<2 * BB * LQ, 256>>>(f_normw, c_normw);

    // (7) out-projection GEMMs
    {
        dim3 grid(DM / 128, (BB * LQ) / 128, 2);
        gemm_tf32<<<grid, 256, GEMM_SMEM>>>(nrm_f, nrm_c, wout_f, wout_c,
                                            fsP, out + BB * LQ * DM,
                                            nullptr, BB * LQ, DM, DIN, DIN, DM, DM, 1);
    }

    // (8) factual final projection with bias
    {
        dim3 grid(DM / 128, (BB * LQ) / 128, 1);
        gemm_tf32<<<grid, 256, GEMM_SMEM>>>(fsP, fsP, wo32P, wo32P, out, out,
                                            outp_b, BB * LQ, DM, DM, DM, DM, DM, 0);
    }
}

// round 16
// speedup vs baseline: 1.0000x; 1.0000x over previous
#include <cuda_runtime.h>
#include <math.h>
#include <stdint.h>

#define BB 4
#define LL 2048
#define LQ 1024
#define DM 512
#define DIN 1024
#define DSTATE 64
#define NH 16
#define HD 64
#define DXBC 1152
#define ZXW 2176      // z + xBC columns kept in g_zx (row stride)
#define WIN_LD 2192   // full in_proj width (z + xBC + dt)
#define CQ 64         // chunk length
#define NCH (LL/CQ)   // 32 chunks per sequence
#define NCHH (2*BB*NH*NCH)   // 4096 chunk-heads

// ---------------- scratch (device globals; allocation-free) ----------------
__device__ float g_u[2][BB*LL*DM];        // rmsnormed inputs (fp32, for dt path)
__device__ float g_u32[2][BB*LL*DM];      // rmsnormed inputs (tf32-rounded, GEMM A)
__device__ float g_zx[2][BB*LL*ZXW];      // in_proj outputs (z + xBC)
__device__ float g_xbc[2][BB*LL*DXBC];    // conv+silu outputs
__device__ float g_dtT[2][NH*BB*LL];      // dt transposed [h][row]
__device__ float g_laT[2][NH*BB*LL];      // log-decay la = -exp(Alog)*dt, [h][row]
__device__ float g_S[NCHH*64*64];         // chunk state contributions [ch][p*64+n]
__device__ float g_h[NCHH*64*64];         // h state entering each chunk
__device__ float g_lc[NCHH*CQ];           // in-chunk inclusive log-decay prefix
__device__ float g_y[2][BB*LL*DIN];       // scan outputs (+D*x)
__device__ float g_nrm[2][BB*LQ*DIN];     // gated rmsnorm (tf32-rounded)
__device__ float g_fs[BB*LQ*DM];          // factual pre-out-proj (tf32-rounded)
__device__ float g_win32[2][DM*ZXW];      // tf32 weights
__device__ float g_wout32[2][DIN*DM];
__device__ float g_wo32[DM*DM];

// ---------------- helpers ----------------
__device__ __forceinline__ float silu(float x) { return x / (1.f + expf(-x)); }

__device__ __forceinline__ uint32_t f2tf32(float x) {
    uint32_t r;
    asm("cvt.rna.tf32.f32 %0, %1;" : "=r"(r) : "f"(x));
    return r;
}
__device__ __forceinline__ float tf32r(float x) { return __uint_as_float(f2tf32(x)); }

__device__ __forceinline__ void mma_tf32(float* c, const uint32_t* a, const uint32_t* b) {
    asm volatile("mma.sync.aligned.m16n8k8.row.col.f32.tf32.tf32.f32 "
        "{%0,%1,%2,%3}, {%4,%5,%6,%7}, {%8,%9}, {%0,%1,%2,%3};"
        : "+f"(c[0]), "+f"(c[1]), "+f"(c[2]), "+f"(c[3])
        : "r"(a[0]), "r"(a[1]), "r"(a[2]), "r"(a[3]), "r"(b[0]), "r"(b[1]));
}

__device__ __forceinline__ void cpa16(float* dst, const float* src) {
    uint32_t d = (uint32_t)__cvta_generic_to_shared(dst);
    asm volatile("cp.async.cg.shared.global [%0], [%1], 16;" :: "r"(d), "l"(src));
}
__device__ __forceinline__ void cpa_commit() { asm volatile("cp.async.commit_group;"); }
template<int N> __device__ __forceinline__ void cpa_wait() {
    asm volatile("cp.async.wait_group %0;" :: "n"(N));
}

// ---------------- launch 0: input rmsnorm + weight cvt (fused) -------------
#define CVT_TOT (2*DM*ZXW + 2*DIN*DM + DM*DM)
__global__ void __launch_bounds__(128) prep_cvt(
    const float* __restrict__ q, const float* __restrict__ kv,
    const float* __restrict__ fw, const float* __restrict__ cw,
    const float* __restrict__ fWin, const float* __restrict__ cWin,
    const float* __restrict__ fWout, const float* __restrict__ cWout,
    const float* __restrict__ oW)
{
    int t = threadIdx.x;
    if (blockIdx.y == 1) {
        for (int i = blockIdx.x * 128 + t; i < CVT_TOT; i += 16384 * 128) {
            int j = i;
            if (j < 2 * DM * ZXW) {
                int reg = j / (DM * ZXW);
                int k = j - reg * (DM * ZXW);
                const float* s = reg ? cWin : fWin;
                int r = k / ZXW, c = k - r * ZXW;
                g_win32[reg][k] = tf32r(s[r * WIN_LD + c]);
            } else if ((j -= 2 * DM * ZXW) < 2 * DIN * DM) {
                int reg = j / (DIN * DM);
                int k = j - reg * (DIN * DM);
                g_wout32[reg][k] = tf32r((reg ? cWout : fWout)[k]);
            } else {
                j -= 2 * DIN * DM;
                g_wo32[j] = tf32r(oW[j]);
            }
        }
        return;
    }

    int row = blockIdx.x;            // 2 * 4 * 2048 rows
    int br  = row >> 13;
    int r   = row & 8191;
    int b   = r >> 11;
    int l   = r & 2047;
    const float* src;
    if (l < LQ) {
        int li = (br == 0) ? l : (LQ - 1 - l);
        src = kv + (b * LQ + li) * DM;
    } else {
        src = q + (b * LQ + (l - LQ)) * DM;
    }
    const float* w = br ? cw : fw;

    float v[4];
    float ss = 0.f;
#pragma unroll
    for (int i = 0; i < 4; i++) { v[i] = src[t + i * 128]; ss += v[i] * v[i]; }

    __shared__ float red[4];
#pragma unroll
    for (int o = 16; o > 0; o >>= 1) ss += __shfl_xor_sync(0xffffffffu, ss, o);
    if ((t & 31) == 0) red[t >> 5] = ss;
    __syncthreads();
    float total = red[0] + red[1] + red[2] + red[3];
    float scale = rsqrtf(total / (float)DM + 1e-5f);

    float* dst   = g_u[br]   + (b * LL + l) * DM;
    float* dst32 = g_u32[br] + (b * LL + l) * DM;
#pragma unroll
    for (int i = 0; i < 4; i++) {
        int idx = t + i * 128;
        float val = v[i] * scale * w[idx];
        dst[idx] = val;
        dst32[idx] = tf32r(val);
    }
}

// ---------------- TF32 GEMM: 128x128x32 tile, 8 warps (64x32), 3-stage -----
// (R14-proven config: 107.5 KB smem -> 2 CTAs/SM)
#define AS_LD 36
#define BS_LD 136
#define A_STG (128 * AS_LD)
#define B_STG (32 * BS_LD)
#define B_OFF (3 * A_STG)
#define GEMM_SMEM ((3 * (A_STG + B_STG)) * 4)

__global__ void __launch_bounds__(256) gemm_tf32(
    const float* __restrict__ A0, const float* __restrict__ A1,
    const float* __restrict__ B0, const float* __restrict__ B1,
    float* __restrict__ C0, float* __restrict__ C1,
    const float* __restrict__ bias,
    int M, int N, int K, int lda, int ldb, int ldc, int roundMask)
{
    extern __shared__ float sm[];
    int z = blockIdx.z;
    const float* A = z ? A1 : A0;
    const float* B = z ? B1 : B0;
    float* C = z ? C1 : C0;
    bool rnd = (roundMask >> z) & 1;

    int tid = threadIdx.x;
    int bm = blockIdx.y * 128, bn = blockIdx.x * 128;

    int w = tid >> 5;
    int lane = tid & 31;
    int g = lane >> 2, cq = lane & 3;
    int mw = (w & 1) * 64;
    int nw = (w >> 1) * 32;

    int a_r = tid >> 3, a_c4 = (tid & 7) * 4;
    int b_r = tid >> 5, b_c4 = (tid & 31) * 4;

    const float* Ag = A + (bm + a_r) * lda + a_c4;
    const float* Bg = B + b_r * ldb + bn + b_c4;

    int nk = K >> 5;

#pragma unroll
    for (int st = 0; st < 2; st++) {
        float* As = sm + st * A_STG;
        float* Bs = sm + B_OFF + st * B_STG;
#pragma unroll
        for (int rr = 0; rr < 4; rr++)
            cpa16(&As[(a_r + rr * 32) * AS_LD + a_c4], Ag + rr * 32 * lda + st * 32);
#pragma unroll
        for (int rr = 0; rr < 4; rr++)
            cpa16(&Bs[(b_r + rr * 8) * BS_LD + b_c4], Bg + (st * 32 + rr * 8) * ldb);
        cpa_commit();
    }

    float acc[4][4][4];
#pragma unroll
    for (int i = 0; i < 4; i++)
#pragma unroll
        for (int j = 0; j < 4; j++)
#pragma unroll
            for (int x = 0; x < 4; x++) acc[i][j][x] = 0.f;

    for (int kt = 0; kt < nk; kt++) {
        if (kt + 1 < nk) cpa_wait<1>(); else cpa_wait<0>();
        __syncthreads();

        if (kt + 2 < nk) {
            int st = (kt + 2) % 3;
            float* As = sm + st * A_STG;
            float* Bs = sm + B_OFF + st * B_STG;
            int k0 = (kt + 2) * 32;
#pragma unroll
            for (int rr = 0; rr < 4; rr++)
                cpa16(&As[(a_r + rr * 32) * AS_LD + a_c4], Ag + rr * 32 * lda + k0);
#pragma unroll
            for (int rr = 0; rr < 4; rr++)
                cpa16(&Bs[(b_r + rr * 8) * BS_LD + b_c4], Bg + (k0 + rr * 8) * ldb);
            cpa_commit();
        }

        const float* As = sm + (kt % 3) * A_STG;
        const float* Bs = sm + B_OFF + (kt % 3) * B_STG;
#pragma unroll
        for (int ks = 0; ks < 4; ks++) {
            int k0 = ks * 8;
            uint32_t af[4][4], bf[4][2];
#pragma unroll
            for (int i = 0; i < 4; i++) {
                int m = mw + i * 16 + g;
                af[i][0] = __float_as_uint(As[m * AS_LD + k0 + cq]);
                af[i][1] = __float_as_uint(As[(m + 8) * AS_LD + k0 + cq]);
                af[i][2] = __float_as_uint(As[m * AS_LD + k0 + cq + 4]);
                af[i][3] = __float_as_uint(As[(m + 8) * AS_LD + k0 + cq + 4]);
            }
#pragma unroll
            for (int j = 0; j < 4; j++) {
                int n = nw + j * 8 + g;
                bf[j][0] = __float_as_uint(Bs[(k0 + cq) * BS_LD + n]);
                bf[j][1] = __float_as_uint(Bs[(k0 + cq + 4) * BS_LD + n]);
            }
#pragma unroll
            for (int i = 0; i < 4; i++)
#pragma unroll
                for (int j = 0; j < 4; j++)
                    mma_tf32(acc[i][j], af[i], bf[j]);
        }
    }

#pragma unroll
    for (int i = 0; i < 4; i++) {
        int m0 = bm + mw + i * 16 + g;
#pragma unroll
        for (int j = 0; j < 4; j++) {
            int n = bn + nw + j * 8 + 2 * cq;
            float b0 = 0.f, b1 = 0.f;
            if (bias) { b0 = bias[n]; b1 = bias[n + 1]; }
            float v00 = acc[i][j][0] + b0, v01 = acc[i][j][1] + b1;
            float v10 = acc[i][j][2] + b0, v11 = acc[i][j][3] + b1;
            if (rnd) { v00 = tf32r(v00); v01 = tf32r(v01); v10 = tf32r(v10); v11 = tf32r(v11); }
            float2 lo = { v00, v01 }, hi = { v10, v11 };
            *(float2*)&C[m0 * ldc + n] = lo;
            *(float2*)&C[(m0 + 8) * ldc + n] = hi;
        }
    }
}

// ---------------- launch 2: conv+silu AND dt-gemm (fused) ------------------
__global__ void __launch_bounds__(288) conv_dt(
    const float* __restrict__ fw, const float* __restrict__ fb,
    const float* __restrict__ cw_, const float* __restrict__ cb,
    const float* __restrict__ fWin, const float* __restrict__ cWin,
    const float* __restrict__ fdtb, const float* __restrict__ cdtb,
    const float* __restrict__ fAl,  const float* __restrict__ cAl)
{
    int br = blockIdx.y;
    int tid = threadIdx.x;

    if (blockIdx.x < BB * LL) {
        const float* w = br ? cw_ : fw;
        const float* bias = br ? cb : fb;
        int row = blockIdx.x;
        int b = row >> 11;
        int l = row & 2047;
        int c4 = tid * 4;

        float4 w0 = *(const float4*)(w + c4 * 4);
        float4 w1 = *(const float4*)(w + c4 * 4 + 4);
        float4 w2 = *(const float4*)(w + c4 * 4 + 8);
        float4 w3 = *(const float4*)(w + c4 * 4 + 12);
        float4 acc = *(const float4*)(bias + c4);

        const float* zbase = g_zx[br] + (size_t)(b * LL) * ZXW + DIN + c4;
#pragma unroll
        for (int j = 0; j < 4; j++) {
            int ls = l - 3 + j;
            if (ls >= 0) {
                float4 x = *(const float4*)(zbase + (size_t)ls * ZXW);
                acc.x += x.x * ((const float*)&w0)[j];
                acc.y += x.y * ((const float*)&w1)[j];
                acc.z += x.z * ((const float*)&w2)[j];
                acc.w += x.w * ((const float*)&w3)[j];
            }
        }
        float4 outv = { silu(acc.x), silu(acc.y), silu(acc.z), silu(acc.w) };
        *(float4*)(g_xbc[br] + (size_t)blockIdx.x * DXBC + c4) = outv;
        return;
    }

    const float* Win = br ? cWin : fWin;
    const float* dtb = br ? cdtb : fdtb;
    const float* Alog = br ? cAl : fAl;
    const float* u = g_u[br];

    __shared__ float Ws[512][16];
    for (int i = tid; i < 512 * 16; i += 288) {
        int k = i >> 4, h = i & 15;
        Ws[k][h] = Win[k * WIN_LD + ZXW + h];
    }
    __syncthreads();
    if (tid >= 256) return;

    int rib = tid >> 4;
    int h   = tid & 15;
    int row = (blockIdx.x - BB * LL) * 16 + rib;
    const float* arow = u + row * DM;

    float a0 = 0.f, a1 = 0.f, a2 = 0.f, a3 = 0.f;
#pragma unroll 4
    for (int k = 0; k < 512; k += 4) {
        a0 += arow[k]     * Ws[k][h];
        a1 += arow[k + 1] * Ws[k + 1][h];
        a2 += arow[k + 2] * Ws[k + 2][h];
        a3 += arow[k + 3] * Ws[k + 3][h];
    }
    float acc = dtb[h] + ((a0 + a1) + (a2 + a3));

    float dt = acc > 20.f ? acc : log1pf(expf(acc));
    g_dtT[br][h * (BB * LL) + row] = dt;
    g_laT[br][h * (BB * LL) + row] = -expf(Alog[h]) * dt;
}

// ---------------- launch 3: chunk state contributions (Phase A) ------------
__global__ void __launch_bounds__(128) chunk_state()
{
    int ch = blockIdx.x;             // 4096
    int c  = ch & 31;
    int h  = (ch >> 5) & 15;
    int b  = (ch >> 9) & 3;
    int br = ch >> 11;

    const float* xbc = g_xbc[br];
    const float* dtp = g_dtT[br] + h * (BB * LL);
    const float* lap = g_laT[br] + h * (BB * LL);
    int rowbase = b * LL + c * CQ;

    __shared__ float Xs[CQ * 64];
    __shared__ float Bw[CQ * 64];
    __shared__ float lc[CQ];
    __shared__ float wgt[CQ];

    int tid = threadIdx.x;

    if (tid < CQ) lc[tid] = lap[rowbase + tid];
    __syncthreads();
    for (int off = 1; off < CQ; off <<= 1) {
        float v = 0.f;
        if (tid < CQ && tid >= off) v = lc[tid - off];
        __syncthreads();
        if (tid < CQ) lc[tid] += v;
        __syncthreads();
    }
    if (tid < CQ) {
        wgt[tid] = dtp[rowbase + tid] * __expf(lc[CQ - 1] - lc[tid]);
        g_lc[ch * CQ + tid] = lc[tid];
    }

    for (int k = tid; k < CQ * 16; k += 128) {
        int s = k >> 4, q = (k & 15) * 4;
        size_t off = (size_t)(rowbase + s) * DXBC;
        *(float4*)&Xs[s * 64 + q] = *(const float4*)(xbc + off + h * 64 + q);
        *(float4*)&Bw[s * 64 + q] = *(const float4*)(xbc + off + 1024 + q);
    }
    __syncthreads();
    for (int k = tid; k < CQ * 16; k += 128) {
        int s = k >> 4, q = (k & 15) * 4;
        float ws = wgt[s];
        float4 v = *(float4*)&Bw[s * 64 + q];
        v.x *= ws; v.y *= ws; v.z *= ws; v.w *= ws;
        *(float4*)&Bw[s * 64 + q] = v;
    }
    __syncthreads();

    int p0 = (tid >> 3) * 4, n0 = (tid & 7) * 8;
    float acc[4][8];
#pragma unroll
    for (int i = 0; i < 4; i++)
#pragma unroll
        for (int j = 0; j < 8; j++) acc[i][j] = 0.f;

    for (int s = 0; s < CQ; s++) {
        float4 xv = *(const float4*)&Xs[s * 64 + p0];
        float4 b0 = *(const float4*)&Bw[s * 64 + n0];
        float4 b1 = *(const float4*)&Bw[s * 64 + n0 + 4];
        const float* xf = (const float*)&xv;
#pragma unroll
        for (int i = 0; i < 4; i++) {
            float x = xf[i];
            acc[i][0] += x * b0.x; acc[i][1] += x * b0.y;
            acc[i][2] += x * b0.z; acc[i][3] += x * b0.w;
            acc[i][4] += x * b1.x; acc[i][5] += x * b1.y;
            acc[i][6] += x * b1.z; acc[i][7] += x * b1.w;
        }
    }

    float* Sp = g_S + (size_t)ch * 4096;
#pragma unroll
    for (int i = 0; i < 4; i++) {
        *(float4*)&Sp[(p0 + i) * 64 + n0]     = *(float4*)&acc[i][0];
        *(float4*)&Sp[(p0 + i) * 64 + n0 + 4] = *(float4*)&acc[i][4];
    }
}

// ---------------- launch 4: inter-chunk state scan (Phase B) ---------------
__global__ void __launch_bounds__(1024) state_scan()
{
    int sh = blockIdx.x;
    int tid = threadIdx.x;
    size_t base = (size_t)sh * NCH * 4096 + tid * 4;

    float4 hr = make_float4(0.f, 0.f, 0.f, 0.f);

    for (int c = 0; c < NCH; c++) {
        size_t off = base + (size_t)c * 4096;
        *(float4*)(g_h + off) = hr;
        float Aend = __expf(g_lc[(sh * NCH + c) * CQ + CQ - 1]);
        float4 s = *(const float4*)(g_S + off);
        hr.x = hr.x * Aend + s.x;
        hr.y = hr.y * Aend + s.y;
        hr.z = hr.z * Aend + s.z;
        hr.w = hr.w * Aend + s.w;
    }
}

// ---------------- launch 5: chunk outputs (Phase C, 256 threads) -----------
#define CO_PAD 65
#define CO_ARR (CQ * CO_PAD)
#define CO_SMEM ((4 * CO_ARR + 3 * CQ) * 4)
__global__ void __launch_bounds__(256) chunk_out(const float* __restrict__ fD,
                                                 const float* __restrict__ cD)
{
    extern __shared__ float smc[];
    float* Cs = smc;
    float* XB = smc + CO_ARR;
    float* G  = smc + 2 * CO_ARR;
    float* Hs = smc + 3 * CO_ARR;
    float* lc = smc + 4 * CO_ARR;
    float* dts = lc + CQ;
    float* elc = dts + CQ;

    int ch = blockIdx.x;
    int c  = ch & 31;
    int h  = (ch >> 5) & 15;
    int b  = (ch >> 9) & 3;
    int br = ch >> 11;

    const float* xbc = g_xbc[br];
    const float* dtp = g_dtT[br] + h * (BB * LL);
    float Dh = (br ? cD : fD)[h];
    int rowbase = b * LL + c * CQ;
    int tid = threadIdx.x;

    if (tid < CQ) {
        float l = g_lc[ch * CQ + tid];
        lc[tid] = l;
        elc[tid] = __expf(l);
        dts[tid] = dtp[rowbase + tid];
    }

    // load C, B (into XB), h_prev — gmem float4, scalar STS (odd stride)
    for (int k = tid; k < CQ * 16; k += 256) {
        int s = k >> 4, q = (k & 15) * 4;
        size_t off = (size_t)(rowbase + s) * DXBC;
        float4 cv = *(const float4*)(xbc + off + 1088 + q);
        float4 bv = *(const float4*)(xbc + off + 1024 + q);
        float4 hv = *(const float4*)(g_h + (size_t)ch * 4096 + s * 64 + q);
        Cs[s * CO_PAD + q]     = cv.x; Cs[s * CO_PAD + q + 1] = cv.y;
        Cs[s * CO_PAD + q + 2] = cv.z; Cs[s * CO_PAD + q + 3] = cv.w;
        XB[s * CO_PAD + q]     = bv.x; XB[s * CO_PAD + q + 1] = bv.y;
        XB[s * CO_PAD + q + 2] = bv.z; XB[s * CO_PAD + q + 3] = bv.w;
        Hs[s * CO_PAD + q]     = hv.x; Hs[s * CO_PAD + q + 1] = hv.y;
        Hs[s * CO_PAD + q + 2] = hv.z; Hs[s * CO_PAD + q + 3] = hv.w;
    }
    __syncthreads();

    // G[t,s] = (C_t . B_s) masked-decayed; thread = 2t x 8s
    {
        int t0 = (tid >> 3) * 2, s0 = (tid & 7) * 8;
        float acc[2][8];
#pragma unroll
        for (int i = 0; i < 2; i++)
#pragma unroll
            for (int j = 0; j < 8; j++) acc[i][j] = 0.f;
        for (int n = 0; n < 64; n++) {
            float cv[2], bv[8];
#pragma unroll
            for (int i = 0; i < 2; i++) cv[i] = Cs[(t0 + i) * CO_PAD + n];
#pragma unroll
            for (int j = 0; j < 8; j++) bv[j] = XB[(s0 + j) * CO_PAD + n];
#pragma unroll
            for (int i = 0; i < 2; i++)
#pragma unroll
                for (int j = 0; j < 8; j++) acc[i][j] += cv[i] * bv[j];
        }
#pragma unroll
        for (int i = 0; i < 2; i++) {
            int t = t0 + i;
#pragma unroll
            for (int j = 0; j < 8; j++) {
                int s = s0 + j;
                float gv = 0.f;
                if (s <= t) gv = acc[i][j] * __expf(lc[t] - lc[s]) * dts[s];
                G[t * CO_PAD + s] = gv;
            }
        }
    }
    __syncthreads();

    // overwrite XB with X (head slice) — scalar STS
    for (int k = tid; k < CQ * 16; k += 256) {
        int s = k >> 4, q = (k & 15) * 4;
        size_t off = (size_t)(rowbase + s) * DXBC;
        float4 xv = *(const float4*)(xbc + off + h * 64 + q);
        XB[s * CO_PAD + q]     = xv.x; XB[s * CO_PAD + q + 1] = xv.y;
        XB[s * CO_PAD + q + 2] = xv.z; XB[s * CO_PAD + q + 3] = xv.w;
    }
    __syncthreads();

    // Y[t,p] = G@X + elc[t]*(C@h^T) + Dh*x; thread = 2t x 8p
    {
        int t0 = (tid >> 3) * 2, p0 = (tid & 7) * 8;
        float y1[2][8], y2[2][8];
#pragma unroll
        for (int i = 0; i < 2; i++)
#pragma unroll
            for (int j = 0; j < 8; j++) { y1[i][j] = 0.f; y2[i][j] = 0.f; }

        for (int s = 0; s < 64; s++) {
            float gv[2], xv[8];
#pragma unroll
            for (int i = 0; i < 2; i++) gv[i] = G[(t0 + i) * CO_PAD + s];
#pragma unroll
            for (int j = 0; j < 8; j++) xv[j] = XB[s * CO_PAD + p0 + j];
#pragma unroll
            for (int i = 0; i < 2; i++) {
                float g = gv[i];
#pragma unroll
                for (int j = 0; j < 8; j++) y1[i][j] += g * xv[j];
            }
        }
        for (int n = 0; n < 64; n++) {
            float cv[2], hv[8];
#pragma unroll
            for (int i = 0; i < 2; i++) cv[i] = Cs[(t0 + i) * CO_PAD + n];
#pragma unroll
            for (int j = 0; j < 8; j++) hv[j] = Hs[(p0 + j) * CO_PAD + n];
#pragma unroll
            for (int i = 0; i < 2; i++)
#pragma unroll
                for (int j = 0; j < 8; j++) y2[i][j] += cv[i] * hv[j];
        }

        float* yp = g_y[br];
#pragma unroll
        for (int i = 0; i < 2; i++) {
            int t = t0 + i;
            float e = elc[t];
            float o[8];
#pragma unroll
            for (int j = 0; j < 8; j++)
                o[j] = y1[i][j] + e * y2[i][j] + Dh * XB[t * CO_PAD + p0 + j];
            float* dst = yp + (size_t)(rowbase + t) * DIN + h * HD + p0;
            *(float4*)dst = *(float4*)&o[0];
            *(float4*)(dst + 4) = *(float4*)&o[4];
        }
    }
}

// ---------------- y*silu(z) + rmsnorm (last LQ tokens, tf32 out) -----------
__global__ void yz_norm(const float* __restrict__ fnw, const float* __restrict__ cnw)
{
    int row = blockIdx.x;            // 2 * 4 * 1024
    int br = row >> 12;
    int r = row & 4095;
    int b = r >> 10;
    int lq = r & 1023;
    int l = lq + LQ;
    const float* nw = br ? cnw : fnw;
    const float* yrow = g_y[br] + (b * LL + l) * DIN;
    const float* zrow = g_zx[br] + (b * LL + l) * ZXW;

    int t = threadIdx.x;             // 256
    float v[4];
    float ss = 0.f;
#pragma unroll
    for (int i = 0; i < 4; i++) {
        int idx = t + i * 256;
        float z = zrow[idx];
        float val = yrow[idx] * silu(z);
        v[i] = val;
        ss += val * val;
    }

    __shared__ float red[8];
#pragma unroll
    for (int o = 16; o > 0; o >>= 1) ss += __shfl_xor_sync(0xffffffffu, ss, o);
    if ((t & 31) == 0) red[t >> 5] = ss;
    __syncthreads();
    float total = 0.f;
#pragma unroll
    for (int i = 0; i < 8; i++) total += red[i];
    float scale = rsqrtf(total / (float)DIN + 1e-5f);

    float* dst = g_nrm[br] + ((b << 10) + lq) * DIN;
#pragma unroll
    for (int i = 0; i < 4; i++) {
        int idx = t + i * 256;
        dst[idx] = tf32r(v[i] * scale * nw[idx]);
    }
}

// ---------------- launch ----------------------------------------------------
extern "C" void kernel_launch(void* const* d_in, const int* in_sizes, int n_in,
                              void* d_out, int out_size)
{
    const float* query   = (const float*)d_in[0];
    const float* kv      = (const float*)d_in[1];
    const float* fnorm_w = (const float*)d_in[2];
    const float* cnorm_w = (const float*)d_in[3];
    const float* f_Win   = (const float*)d_in[4];
    const float* f_convw = (const float*)d_in[5];
    const float* f_convb = (const float*)d_in[6];
    const float* f_dtb   = (const float*)d_in[7];
    const float* f_Alog  = (const float*)d_in[8];
    const float* f_D     = (const float*)d_in[9];
    const float* f_normw = (const float*)d_in[10];
    const float* f_Wout  = (const float*)d_in[11];
    const float* c_Win   = (const float*)d_in[12];
    const float* c_convw = (const float*)d_in[13];
    const float* c_convb = (const float*)d_in[14];
    const float* c_dtb   = (const float*)d_in[15];
    const float* c_Alog  = (const float*)d_in[16];
    const float* c_D     = (const float*)d_in[17];
    const float* c_normw = (const float*)d_in[18];
    const float* c_Wout  = (const float*)d_in[19];
    const float* outp_w  = (const float*)d_in[20];
    const float* outp_b  = (const float*)d_in[21];
    float* out = (float*)d_out;

    float *uP32, *zxP, *nrmP, *fsP, *win32P, *wout32P, *wo32P;
    cudaGetSymbolAddress((void**)&uP32,   g_u32);
    cudaGetSymbolAddress((void**)&zxP,    g_zx);
    cudaGetSymbolAddress((void**)&nrmP,   g_nrm);
    cudaGetSymbolAddress((void**)&fsP,    g_fs);
    cudaGetSymbolAddress((void**)&win32P, g_win32);
    cudaGetSymbolAddress((void**)&wout32P,g_wout32);
    cudaGetSymbolAddress((void**)&wo32P,  g_wo32);

    cudaFuncSetAttribute(gemm_tf32, cudaFuncAttributeMaxDynamicSharedMemorySize, GEMM_SMEM);
    cudaFuncSetAttribute(chunk_out, cudaFuncAttributeMaxDynamicSharedMemorySize, CO_SMEM);

    float* u32_f = uP32;
    float* u32_c = uP32 + BB * LL * DM;
    float* zx_f = zxP;
    float* zx_c = zxP + BB * LL * ZXW;
    float* nrm_f = nrmP;
    float* nrm_c = nrmP + BB * LQ * DIN;
    float* win_f = win32P;
    float* win_c = win32P + DM * ZXW;
    float* wout_f = wout32P;
    float* wout_c = wout32P + DIN * DM;

    // (0) input rmsnorm + weight cvt (fused)
    {
        dim3 grid(2 * BB * LL, 2);
        prep_cvt<<<grid, 128>>>(query, kv, fnorm_w, cnorm_w,
                                f_Win, c_Win, f_Wout, c_Wout, outp_w);
    }

    // (1) in_proj GEMMs
    {
        dim3 grid(ZXW / 128, (BB * LL) / 128, 2);
        gemm_tf32<<<grid, 256, GEMM_SMEM>>>(u32_f, u32_c, win_f, win_c, zx_f, zx_c,
                                            nullptr, BB * LL, ZXW, DM, DM, ZXW, ZXW, 0);
    }

    // (2) conv+silu + dt/la (fused)
    {
        dim3 grid(BB * LL + (BB * LL) / 16, 2);
        conv_dt<<<grid, 288>>>(f_convw, f_convb, c_convw, c_convb,
                               f_Win, c_Win, f_dtb, c_dtb, f_Alog, c_Alog);
    }

    // (3) chunked SSD phase A: chunk states
    chunk_state<<<NCHH, 128>>>();

    // (4) phase B: inter-chunk state scan
    state_scan<<<2 * BB * NH, 1024>>>();

    // (5) phase C: chunk outputs (256 threads)
    chunk_out<<<NCHH, 256, CO_SMEM>>>(f_D, c_D);

    // (6) gate + rmsnorm
    yz_norm<<<2 * BB * LQ, 256>>>(f_normw, c_normw);

    // (7) out-projection GEMMs
    {
        dim3 grid(DM / 128, (BB * LQ) / 128, 2);
        gemm_tf32<<<grid, 256, GEMM_SMEM>>>(nrm_f, nrm_c, wout_f, wout_c,
                                            fsP, out + BB * LQ * DM,
                                            nullptr, BB * LQ, DM, DIN, DIN, DM, DM, 1);
    }

    // (8) factual final projection with bias
    {
        dim3 grid(DM / 128, (BB * LQ) / 128, 1);
        gemm_tf32<<<grid, 256, GEMM_SMEM>>>(fsP, fsP, wo32P, wo32P, out, out,
                                            outp_b, BB * LQ, DM, DM, DM, DM, DM, 0);
    }
}

// round 17
// speedup vs baseline: 1.1502x; 1.1502x over previous
#include <cuda_runtime.h>
#include <math.h>
#include <stdint.h>

#define BB 4
#define LL 2048
#define LQ 1024
#define DM 512
#define DIN 1024
#define DSTATE 64
#define NH 16
#define HD 64
#define DXBC 1152
#define ZXW 2176      // z + xBC columns kept in g_zx (row stride)
#define WIN_LD 2192   // full in_proj width (z + xBC + dt)
#define CQ 64         // chunk length
#define NCH (LL/CQ)   // 32 chunks per sequence
#define NCHH (2*BB*NH*NCH)   // 4096 chunk-heads

// ---------------- scratch (device globals; allocation-free) ----------------
__device__ float g_u[2][BB*LL*DM];        // rmsnormed inputs (fp32, for dt path)
__device__ float g_u32[2][BB*LL*DM];      // rmsnormed inputs (tf32-rounded, GEMM A)
__device__ float g_zx[2][BB*LL*ZXW];      // in_proj outputs (z + xBC)
__device__ float g_xbc[2][BB*LL*DXBC];    // conv+silu outputs
__device__ float g_dtT[2][NH*BB*LL];      // dt transposed [h][row]
__device__ float g_laT[2][NH*BB*LL];      // log-decay la = -exp(Alog)*dt, [h][row]
__device__ float g_S[NCHH*64*64];         // chunk state contributions [ch][p*64+n]
__device__ float g_h[NCHH*64*64];         // h state entering each chunk
__device__ float g_lc[NCHH*CQ];           // in-chunk inclusive log-decay prefix
__device__ float g_y[2][BB*LL*DIN];       // scan outputs (+D*x)
__device__ float g_nrm[2][BB*LQ*DIN];     // gated rmsnorm (tf32-rounded)
__device__ float g_fs[BB*LQ*DM];          // factual pre-out-proj (tf32-rounded)
__device__ float g_win32[2][DM*ZXW];      // tf32 weights
__device__ float g_wout32[2][DIN*DM];
__device__ float g_wo32[DM*DM];

// ---------------- helpers ----------------
__device__ __forceinline__ float silu(float x) { return x / (1.f + expf(-x)); }

__device__ __forceinline__ uint32_t f2tf32(float x) {
    uint32_t r;
    asm("cvt.rna.tf32.f32 %0, %1;" : "=r"(r) : "f"(x));
    return r;
}
__device__ __forceinline__ float tf32r(float x) { return __uint_as_float(f2tf32(x)); }

__device__ __forceinline__ void mma_tf32(float* c, const uint32_t* a, const uint32_t* b) {
    asm volatile("mma.sync.aligned.m16n8k8.row.col.f32.tf32.tf32.f32 "
        "{%0,%1,%2,%3}, {%4,%5,%6,%7}, {%8,%9}, {%0,%1,%2,%3};"
        : "+f"(c[0]), "+f"(c[1]), "+f"(c[2]), "+f"(c[3])
        : "r"(a[0]), "r"(a[1]), "r"(a[2]), "r"(a[3]), "r"(b[0]), "r"(b[1]));
}

__device__ __forceinline__ void cpa16(float* dst, const float* src) {
    uint32_t d = (uint32_t)__cvta_generic_to_shared(dst);
    asm volatile("cp.async.cg.shared.global [%0], [%1], 16;" :: "r"(d), "l"(src));
}
__device__ __forceinline__ void cpa_commit() { asm volatile("cp.async.commit_group;"); }
template<int N> __device__ __forceinline__ void cpa_wait() {
    asm volatile("cp.async.wait_group %0;" :: "n"(N));
}

// ---------------- launch 0: input rmsnorm + weight cvt (fused) -------------
#define CVT_TOT (2*DM*ZXW + 2*DIN*DM + DM*DM)
__global__ void __launch_bounds__(128) prep_cvt(
    const float* __restrict__ q, const float* __restrict__ kv,
    const float* __restrict__ fw, const float* __restrict__ cw,
    const float* __restrict__ fWin, const float* __restrict__ cWin,
    const float* __restrict__ fWout, const float* __restrict__ cWout,
    const float* __restrict__ oW)
{
    int t = threadIdx.x;
    if (blockIdx.y == 1) {
        for (int i = blockIdx.x * 128 + t; i < CVT_TOT; i += 16384 * 128) {
            int j = i;
            if (j < 2 * DM * ZXW) {
                int reg = j / (DM * ZXW);
                int k = j - reg * (DM * ZXW);
                const float* s = reg ? cWin : fWin;
                int r = k / ZXW, c = k - r * ZXW;
                g_win32[reg][k] = tf32r(s[r * WIN_LD + c]);
            } else if ((j -= 2 * DM * ZXW) < 2 * DIN * DM) {
                int reg = j / (DIN * DM);
                int k = j - reg * (DIN * DM);
                g_wout32[reg][k] = tf32r((reg ? cWout : fWout)[k]);
            } else {
                j -= 2 * DIN * DM;
                g_wo32[j] = tf32r(oW[j]);
            }
        }
        return;
    }

    int row = blockIdx.x;            // 2 * 4 * 2048 rows
    int br  = row >> 13;
    int r   = row & 8191;
    int b   = r >> 11;
    int l   = r & 2047;
    const float* src;
    if (l < LQ) {
        int li = (br == 0) ? l : (LQ - 1 - l);
        src = kv + (b * LQ + li) * DM;
    } else {
        src = q + (b * LQ + (l - LQ)) * DM;
    }
    const float* w = br ? cw : fw;

    float v[4];
    float ss = 0.f;
#pragma unroll
    for (int i = 0; i < 4; i++) { v[i] = src[t + i * 128]; ss += v[i] * v[i]; }

    __shared__ float red[4];
#pragma unroll
    for (int o = 16; o > 0; o >>= 1) ss += __shfl_xor_sync(0xffffffffu, ss, o);
    if ((t & 31) == 0) red[t >> 5] = ss;
    __syncthreads();
    float total = red[0] + red[1] + red[2] + red[3];
    float scale = rsqrtf(total / (float)DM + 1e-5f);

    float* dst   = g_u[br]   + (b * LL + l) * DM;
    float* dst32 = g_u32[br] + (b * LL + l) * DM;
#pragma unroll
    for (int i = 0; i < 4; i++) {
        int idx = t + i * 128;
        float val = v[i] * scale * w[idx];
        dst[idx] = val;
        dst32[idx] = tf32r(val);
    }
}

// ---------------- TF32 GEMM: 128x128x32 tile, 8 warps (64x32), 3-stage -----
#define AS_LD 36
#define BS_LD 136
#define A_STG (128 * AS_LD)
#define B_STG (32 * BS_LD)
#define B_OFF (3 * A_STG)
#define GEMM_SMEM ((3 * (A_STG + B_STG)) * 4)

__global__ void __launch_bounds__(256) gemm_tf32(
    const float* __restrict__ A0, const float* __restrict__ A1,
    const float* __restrict__ B0, const float* __restrict__ B1,
    float* __restrict__ C0, float* __restrict__ C1,
    const float* __restrict__ bias,
    int M, int N, int K, int lda, int ldb, int ldc, int roundMask)
{
    extern __shared__ float sm[];
    int z = blockIdx.z;
    const float* A = z ? A1 : A0;
    const float* B = z ? B1 : B0;
    float* C = z ? C1 : C0;
    bool rnd = (roundMask >> z) & 1;

    int tid = threadIdx.x;
    int bm = blockIdx.y * 128, bn = blockIdx.x * 128;

    int w = tid >> 5;
    int lane = tid & 31;
    int g = lane >> 2, cq = lane & 3;
    int mw = (w & 1) * 64;
    int nw = (w >> 1) * 32;

    int a_r = tid >> 3, a_c4 = (tid & 7) * 4;
    int b_r = tid >> 5, b_c4 = (tid & 31) * 4;

    const float* Ag = A + (bm + a_r) * lda + a_c4;
    const float* Bg = B + b_r * ldb + bn + b_c4;

    int nk = K >> 5;

#pragma unroll
    for (int st = 0; st < 2; st++) {
        float* As = sm + st * A_STG;
        float* Bs = sm + B_OFF + st * B_STG;
#pragma unroll
        for (int rr = 0; rr < 4; rr++)
            cpa16(&As[(a_r + rr * 32) * AS_LD + a_c4], Ag + rr * 32 * lda + st * 32);
#pragma unroll
        for (int rr = 0; rr < 4; rr++)
            cpa16(&Bs[(b_r + rr * 8) * BS_LD + b_c4], Bg + (st * 32 + rr * 8) * ldb);
        cpa_commit();
    }

    float acc[4][4][4];
#pragma unroll
    for (int i = 0; i < 4; i++)
#pragma unroll
        for (int j = 0; j < 4; j++)
#pragma unroll
            for (int x = 0; x < 4; x++) acc[i][j][x] = 0.f;

    for (int kt = 0; kt < nk; kt++) {
        if (kt + 1 < nk) cpa_wait<1>(); else cpa_wait<0>();
        __syncthreads();

        if (kt + 2 < nk) {
            int st = (kt + 2) % 3;
            float* As = sm + st * A_STG;
            float* Bs = sm + B_OFF + st * B_STG;
            int k0 = (kt + 2) * 32;
#pragma unroll
            for (int rr = 0; rr < 4; rr++)
                cpa16(&As[(a_r + rr * 32) * AS_LD + a_c4], Ag + rr * 32 * lda + k0);
#pragma unroll
            for (int rr = 0; rr < 4; rr++)
                cpa16(&Bs[(b_r + rr * 8) * BS_LD + b_c4], Bg + (k0 + rr * 8) * ldb);
            cpa_commit();
        }

        const float* As = sm + (kt % 3) * A_STG;
        const float* Bs = sm + B_OFF + (kt % 3) * B_STG;
#pragma unroll
        for (int ks = 0; ks < 4; ks++) {
            int k0 = ks * 8;
            uint32_t af[4][4], bf[4][2];
#pragma unroll
            for (int i = 0; i < 4; i++) {
                int m = mw + i * 16 + g;
                af[i][0] = __float_as_uint(As[m * AS_LD + k0 + cq]);
                af[i][1] = __float_as_uint(As[(m + 8) * AS_LD + k0 + cq]);
                af[i][2] = __float_as_uint(As[m * AS_LD + k0 + cq + 4]);
                af[i][3] = __float_as_uint(As[(m + 8) * AS_LD + k0 + cq + 4]);
            }
#pragma unroll
            for (int j = 0; j < 4; j++) {
                int n = nw + j * 8 + g;
                bf[j][0] = __float_as_uint(Bs[(k0 + cq) * BS_LD + n]);
                bf[j][1] = __float_as_uint(Bs[(k0 + cq + 4) * BS_LD + n]);
            }
#pragma unroll
            for (int i = 0; i < 4; i++)
#pragma unroll
                for (int j = 0; j < 4; j++)
                    mma_tf32(acc[i][j], af[i], bf[j]);
        }
    }

#pragma unroll
    for (int i = 0; i < 4; i++) {
        int m0 = bm + mw + i * 16 + g;
#pragma unroll
        for (int j = 0; j < 4; j++) {
            int n = bn + nw + j * 8 + 2 * cq;
            float b0 = 0.f, b1 = 0.f;
            if (bias) { b0 = bias[n]; b1 = bias[n + 1]; }
            float v00 = acc[i][j][0] + b0, v01 = acc[i][j][1] + b1;
            float v10 = acc[i][j][2] + b0, v11 = acc[i][j][3] + b1;
            if (rnd) { v00 = tf32r(v00); v01 = tf32r(v01); v10 = tf32r(v10); v11 = tf32r(v11); }
            float2 lo = { v00, v01 }, hi = { v10, v11 };
            *(float2*)&C[m0 * ldc + n] = lo;
            *(float2*)&C[(m0 + 8) * ldc + n] = hi;
        }
    }
}

// ---------------- launch 2: conv+silu AND dt-gemm (fused) ------------------
__global__ void __launch_bounds__(288) conv_dt(
    const float* __restrict__ fw, const float* __restrict__ fb,
    const float* __restrict__ cw_, const float* __restrict__ cb,
    const float* __restrict__ fWin, const float* __restrict__ cWin,
    const float* __restrict__ fdtb, const float* __restrict__ cdtb,
    const float* __restrict__ fAl,  const float* __restrict__ cAl)
{
    int br = blockIdx.y;
    int tid = threadIdx.x;

    if (blockIdx.x < BB * LL) {
        const float* w = br ? cw_ : fw;
        const float* bias = br ? cb : fb;
        int row = blockIdx.x;
        int b = row >> 11;
        int l = row & 2047;
        int c4 = tid * 4;

        float4 w0 = *(const float4*)(w + c4 * 4);
        float4 w1 = *(const float4*)(w + c4 * 4 + 4);
        float4 w2 = *(const float4*)(w + c4 * 4 + 8);
        float4 w3 = *(const float4*)(w + c4 * 4 + 12);
        float4 acc = *(const float4*)(bias + c4);

        const float* zbase = g_zx[br] + (size_t)(b * LL) * ZXW + DIN + c4;
#pragma unroll
        for (int j = 0; j < 4; j++) {
            int ls = l - 3 + j;
            if (ls >= 0) {
                float4 x = *(const float4*)(zbase + (size_t)ls * ZXW);
                acc.x += x.x * ((const float*)&w0)[j];
                acc.y += x.y * ((const float*)&w1)[j];
                acc.z += x.z * ((const float*)&w2)[j];
                acc.w += x.w * ((const float*)&w3)[j];
            }
        }
        float4 outv = { silu(acc.x), silu(acc.y), silu(acc.z), silu(acc.w) };
        *(float4*)(g_xbc[br] + (size_t)blockIdx.x * DXBC + c4) = outv;
        return;
    }

    const float* Win = br ? cWin : fWin;
    const float* dtb = br ? cdtb : fdtb;
    const float* Alog = br ? cAl : fAl;
    const float* u = g_u[br];

    __shared__ float Ws[512][16];
    for (int i = tid; i < 512 * 16; i += 288) {
        int k = i >> 4, h = i & 15;
        Ws[k][h] = Win[k * WIN_LD + ZXW + h];
    }
    __syncthreads();
    if (tid >= 256) return;

    int rib = tid >> 4;
    int h   = tid & 15;
    int row = (blockIdx.x - BB * LL) * 16 + rib;
    const float* arow = u + row * DM;

    float a0 = 0.f, a1 = 0.f, a2 = 0.f, a3 = 0.f;
#pragma unroll 4
    for (int k = 0; k < 512; k += 4) {
        a0 += arow[k]     * Ws[k][h];
        a1 += arow[k + 1] * Ws[k + 1][h];
        a2 += arow[k + 2] * Ws[k + 2][h];
        a3 += arow[k + 3] * Ws[k + 3][h];
    }
    float acc = dtb[h] + ((a0 + a1) + (a2 + a3));

    float dt = acc > 20.f ? acc : log1pf(expf(acc));
    g_dtT[br][h * (BB * LL) + row] = dt;
    g_laT[br][h * (BB * LL) + row] = -expf(Alog[h]) * dt;
}

// ---------------- launch 3: chunk state contributions (Phase A) ------------
__global__ void __launch_bounds__(128) chunk_state()
{
    int ch = blockIdx.x;             // 4096
    int c  = ch & 31;
    int h  = (ch >> 5) & 15;
    int b  = (ch >> 9) & 3;
    int br = ch >> 11;

    const float* xbc = g_xbc[br];
    const float* dtp = g_dtT[br] + h * (BB * LL);
    const float* lap = g_laT[br] + h * (BB * LL);
    int rowbase = b * LL + c * CQ;

    __shared__ float Xs[CQ * 64];
    __shared__ float Bw[CQ * 64];
    __shared__ float lc[CQ];
    __shared__ float wgt[CQ];

    int tid = threadIdx.x;

    if (tid < CQ) lc[tid] = lap[rowbase + tid];
    __syncthreads();
    for (int off = 1; off < CQ; off <<= 1) {
        float v = 0.f;
        if (tid < CQ && tid >= off) v = lc[tid - off];
        __syncthreads();
        if (tid < CQ) lc[tid] += v;
        __syncthreads();
    }
    if (tid < CQ) {
        wgt[tid] = dtp[rowbase + tid] * __expf(lc[CQ - 1] - lc[tid]);
        g_lc[ch * CQ + tid] = lc[tid];
    }

    for (int k = tid; k < CQ * 16; k += 128) {
        int s = k >> 4, q = (k & 15) * 4;
        size_t off = (size_t)(rowbase + s) * DXBC;
        *(float4*)&Xs[s * 64 + q] = *(const float4*)(xbc + off + h * 64 + q);
        *(float4*)&Bw[s * 64 + q] = *(const float4*)(xbc + off + 1024 + q);
    }
    __syncthreads();
    for (int k = tid; k < CQ * 16; k += 128) {
        int s = k >> 4, q = (k & 15) * 4;
        float ws = wgt[s];
        float4 v = *(float4*)&Bw[s * 64 + q];
        v.x *= ws; v.y *= ws; v.z *= ws; v.w *= ws;
        *(float4*)&Bw[s * 64 + q] = v;
    }
    __syncthreads();

    int p0 = (tid >> 3) * 4, n0 = (tid & 7) * 8;
    float acc[4][8];
#pragma unroll
    for (int i = 0; i < 4; i++)
#pragma unroll
        for (int j = 0; j < 8; j++) acc[i][j] = 0.f;

    for (int s = 0; s < CQ; s++) {
        float4 xv = *(const float4*)&Xs[s * 64 + p0];
        float4 b0 = *(const float4*)&Bw[s * 64 + n0];
        float4 b1 = *(const float4*)&Bw[s * 64 + n0 + 4];
        const float* xf = (const float*)&xv;
#pragma unroll
        for (int i = 0; i < 4; i++) {
            float x = xf[i];
            acc[i][0] += x * b0.x; acc[i][1] += x * b0.y;
            acc[i][2] += x * b0.z; acc[i][3] += x * b0.w;
            acc[i][4] += x * b1.x; acc[i][5] += x * b1.y;
            acc[i][6] += x * b1.z; acc[i][7] += x * b1.w;
        }
    }

    float* Sp = g_S + (size_t)ch * 4096;
#pragma unroll
    for (int i = 0; i < 4; i++) {
        *(float4*)&Sp[(p0 + i) * 64 + n0]     = *(float4*)&acc[i][0];
        *(float4*)&Sp[(p0 + i) * 64 + n0 + 4] = *(float4*)&acc[i][4];
    }
}

// ---------------- launch 4: inter-chunk state scan (Phase B) ---------------
__global__ void __launch_bounds__(1024) state_scan()
{
    int sh = blockIdx.x;
    int tid = threadIdx.x;
    size_t base = (size_t)sh * NCH * 4096 + tid * 4;

    float4 hr = make_float4(0.f, 0.f, 0.f, 0.f);

    for (int c = 0; c < NCH; c++) {
        size_t off = base + (size_t)c * 4096;
        *(float4*)(g_h + off) = hr;
        float Aend = __expf(g_lc[(sh * NCH + c) * CQ + CQ - 1]);
        float4 s = *(const float4*)(g_S + off);
        hr.x = hr.x * Aend + s.x;
        hr.y = hr.y * Aend + s.y;
        hr.z = hr.z * Aend + s.z;
        hr.w = hr.w * Aend + s.w;
    }
}

// ---------------- launch 5: chunk outputs (Phase C, 128 thr + causal skip) -
#define CO_PAD 65
#define CO_ARR (CQ * CO_PAD)
#define CO_SMEM ((4 * CO_ARR + 3 * CQ) * 4)
__global__ void __launch_bounds__(128) chunk_out(const float* __restrict__ fD,
                                                 const float* __restrict__ cD)
{
    extern __shared__ float smc[];
    float* Cs = smc;
    float* XB = smc + CO_ARR;
    float* G  = smc + 2 * CO_ARR;
    float* Hs = smc + 3 * CO_ARR;
    float* lc = smc + 4 * CO_ARR;
    float* dts = lc + CQ;
    float* elc = dts + CQ;

    int ch = blockIdx.x;
    int c  = ch & 31;
    int h  = (ch >> 5) & 15;
    int b  = (ch >> 9) & 3;
    int br = ch >> 11;

    const float* xbc = g_xbc[br];
    const float* dtp = g_dtT[br] + h * (BB * LL);
    float Dh = (br ? cD : fD)[h];
    int rowbase = b * LL + c * CQ;
    int tid = threadIdx.x;

    if (tid < CQ) {
        float l = g_lc[ch * CQ + tid];
        lc[tid] = l;
        elc[tid] = __expf(l);
        dts[tid] = dtp[rowbase + tid];
    }

    // load C, B (into XB), h_prev — gmem float4, scalar STS (odd stride)
    for (int k = tid; k < CQ * 16; k += 128) {
        int s = k >> 4, q = (k & 15) * 4;
        size_t off = (size_t)(rowbase + s) * DXBC;
        float4 cv = *(const float4*)(xbc + off + 1088 + q);
        float4 bv = *(const float4*)(xbc + off + 1024 + q);
        float4 hv = *(const float4*)(g_h + (size_t)ch * 4096 + s * 64 + q);
        Cs[s * CO_PAD + q]     = cv.x; Cs[s * CO_PAD + q + 1] = cv.y;
        Cs[s * CO_PAD + q + 2] = cv.z; Cs[s * CO_PAD + q + 3] = cv.w;
        XB[s * CO_PAD + q]     = bv.x; XB[s * CO_PAD + q + 1] = bv.y;
        XB[s * CO_PAD + q + 2] = bv.z; XB[s * CO_PAD + q + 3] = bv.w;
        Hs[s * CO_PAD + q]     = hv.x; Hs[s * CO_PAD + q + 1] = hv.y;
        Hs[s * CO_PAD + q + 2] = hv.z; Hs[s * CO_PAD + q + 3] = hv.w;
    }
    __syncthreads();

    // G[t,s] = (C_t . B_s) masked-decayed; thread = 4t x 8s
    // causality: tiles entirely above the diagonal (s0 > t0+3) are pure zeros
    {
        int t0 = (tid >> 3) * 4, s0 = (tid & 7) * 8;
        if (s0 > t0 + 3) {
#pragma unroll
            for (int i = 0; i < 4; i++)
#pragma unroll
                for (int j = 0; j < 8; j++) G[(t0 + i) * CO_PAD + s0 + j] = 0.f;
        } else {
            float acc[4][8];
#pragma unroll
            for (int i = 0; i < 4; i++)
#pragma unroll
                for (int j = 0; j < 8; j++) acc[i][j] = 0.f;
            for (int n = 0; n < 64; n++) {
                float cv[4], bv[8];
#pragma unroll
                for (int i = 0; i < 4; i++) cv[i] = Cs[(t0 + i) * CO_PAD + n];
#pragma unroll
                for (int j = 0; j < 8; j++) bv[j] = XB[(s0 + j) * CO_PAD + n];
#pragma unroll
                for (int i = 0; i < 4; i++)
#pragma unroll
                    for (int j = 0; j < 8; j++) acc[i][j] += cv[i] * bv[j];
            }
#pragma unroll
            for (int i = 0; i < 4; i++) {
                int t = t0 + i;
#pragma unroll
                for (int j = 0; j < 8; j++) {
                    int s = s0 + j;
                    float gv = 0.f;
                    if (s <= t) gv = acc[i][j] * __expf(lc[t] - lc[s]) * dts[s];
                    G[t * CO_PAD + s] = gv;
                }
            }
        }
    }
    __syncthreads();

    // overwrite XB with X (head slice) — scalar STS
    for (int k = tid; k < CQ * 16; k += 128) {
        int s = k >> 4, q = (k & 15) * 4;
        size_t off = (size_t)(rowbase + s) * DXBC;
        float4 xv = *(const float4*)(xbc + off + h * 64 + q);
        XB[s * CO_PAD + q]     = xv.x; XB[s * CO_PAD + q + 1] = xv.y;
        XB[s * CO_PAD + q + 2] = xv.z; XB[s * CO_PAD + q + 3] = xv.w;
    }
    __syncthreads();

    // Y[t,p] = G@X + elc[t]*(C@h^T) + Dh*x; thread = 4t x 8p
    // causality: G rows t0..t0+3 are zero for s > t0+3 -> truncate s-loop
    {
        int t0 = (tid >> 3) * 4, p0 = (tid & 7) * 8;
        float y1[4][8], y2[4][8];
#pragma unroll
        for (int i = 0; i < 4; i++)
#pragma unroll
            for (int j = 0; j < 8; j++) { y1[i][j] = 0.f; y2[i][j] = 0.f; }

        int smax = t0 + 4;
        for (int s = 0; s < smax; s++) {
            float gv[4], xv[8];
#pragma unroll
            for (int i = 0; i < 4; i++) gv[i] = G[(t0 + i) * CO_PAD + s];
#pragma unroll
            for (int j = 0; j < 8; j++) xv[j] = XB[s * CO_PAD + p0 + j];
#pragma unroll
            for (int i = 0; i < 4; i++) {
                float g = gv[i];
#pragma unroll
                for (int j = 0; j < 8; j++) y1[i][j] += g * xv[j];
            }
        }
        for (int n = 0; n < 64; n++) {
            float cv[4], hv[8];
#pragma unroll
            for (int i = 0; i < 4; i++) cv[i] = Cs[(t0 + i) * CO_PAD + n];
#pragma unroll
            for (int j = 0; j < 8; j++) hv[j] = Hs[(p0 + j) * CO_PAD + n];
#pragma unroll
            for (int i = 0; i < 4; i++)
#pragma unroll
                for (int j = 0; j < 8; j++) y2[i][j] += cv[i] * hv[j];
        }

        float* yp = g_y[br];
#pragma unroll
        for (int i = 0; i < 4; i++) {
            int t = t0 + i;
            float e = elc[t];
            float o[8];
#pragma unroll
            for (int j = 0; j < 8; j++)
                o[j] = y1[i][j] + e * y2[i][j] + Dh * XB[t * CO_PAD + p0 + j];
            float* dst = yp + (size_t)(rowbase + t) * DIN + h * HD + p0;
            *(float4*)dst = *(float4*)&o[0];
            *(float4*)(dst + 4) = *(float4*)&o[4];
        }
    }
}

// ---------------- y*silu(z) + rmsnorm (last LQ tokens, tf32 out) -----------
__global__ void yz_norm(const float* __restrict__ fnw, const float* __restrict__ cnw)
{
    int row = blockIdx.x;            // 2 * 4 * 1024
    int br = row >> 12;
    int r = row & 4095;
    int b = r >> 10;
    int lq = r & 1023;
    int l = lq + LQ;
    const float* nw = br ? cnw : fnw;
    const float* yrow = g_y[br] + (b * LL + l) * DIN;
    const float* zrow = g_zx[br] + (b * LL + l) * ZXW;

    int t = threadIdx.x;             // 256
    float v[4];
    float ss = 0.f;
#pragma unroll
    for (int i = 0; i < 4; i++) {
        int idx = t + i * 256;
        float z = zrow[idx];
        float val = yrow[idx] * silu(z);
        v[i] = val;
        ss += val * val;
    }

    __shared__ float red[8];
#pragma unroll
    for (int o = 16; o > 0; o >>= 1) ss += __shfl_xor_sync(0xffffffffu, ss, o);
    if ((t & 31) == 0) red[t >> 5] = ss;
    __syncthreads();
    float total = 0.f;
#pragma unroll
    for (int i = 0; i < 8; i++) total += red[i];
    float scale = rsqrtf(total / (float)DIN + 1e-5f);

    float* dst = g_nrm[br] + ((b << 10) + lq) * DIN;
#pragma unroll
    for (int i = 0; i < 4; i++) {
        int idx = t + i * 256;
        dst[idx] = tf32r(v[i] * scale * nw[idx]);
    }
}

// ---------------- launch ----------------------------------------------------
extern "C" void kernel_launch(void* const* d_in, const int* in_sizes, int n_in,
                              void* d_out, int out_size)
{
    const float* query   = (const float*)d_in[0];
    const float* kv      = (const float*)d_in[1];
    const float* fnorm_w = (const float*)d_in[2];
    const float* cnorm_w = (const float*)d_in[3];
    const float* f_Win   = (const float*)d_in[4];
    const float* f_convw = (const float*)d_in[5];
    const float* f_convb = (const float*)d_in[6];
    const float* f_dtb   = (const float*)d_in[7];
    const float* f_Alog  = (const float*)d_in[8];
    const float* f_D     = (const float*)d_in[9];
    const float* f_normw = (const float*)d_in[10];
    const float* f_Wout  = (const float*)d_in[11];
    const float* c_Win   = (const float*)d_in[12];
    const float* c_convw = (const float*)d_in[13];
    const float* c_convb = (const float*)d_in[14];
    const float* c_dtb   = (const float*)d_in[15];
    const float* c_Alog  = (const float*)d_in[16];
    const float* c_D     = (const float*)d_in[17];
    const float* c_normw = (const float*)d_in[18];
    const float* c_Wout  = (const float*)d_in[19];
    const float* outp_w  = (const float*)d_in[20];
    const float* outp_b  = (const float*)d_in[21];
    float* out = (float*)d_out;

    float *uP32, *zxP, *nrmP, *fsP, *win32P, *wout32P, *wo32P;
    cudaGetSymbolAddress((void**)&uP32,   g_u32);
    cudaGetSymbolAddress((void**)&zxP,    g_zx);
    cudaGetSymbolAddress((void**)&nrmP,   g_nrm);
    cudaGetSymbolAddress((void**)&fsP,    g_fs);
    cudaGetSymbolAddress((void**)&win32P, g_win32);
    cudaGetSymbolAddress((void**)&wout32P,g_wout32);
    cudaGetSymbolAddress((void**)&wo32P,  g_wo32);

    cudaFuncSetAttribute(gemm_tf32, cudaFuncAttributeMaxDynamicSharedMemorySize, GEMM_SMEM);
    cudaFuncSetAttribute(chunk_out, cudaFuncAttributeMaxDynamicSharedMemorySize, CO_SMEM);

    float* u32_f = uP32;
    float* u32_c = uP32 + BB * LL * DM;
    float* zx_f = zxP;
    float* zx_c = zxP + BB * LL * ZXW;
    float* nrm_f = nrmP;
    float* nrm_c = nrmP + BB * LQ * DIN;
    float* win_f = win32P;
    float* win_c = win32P + DM * ZXW;
    float* wout_f = wout32P;
    float* wout_c = wout32P + DIN * DM;

    // (0) input rmsnorm + weight cvt (fused)
    {
        dim3 grid(2 * BB * LL, 2);
        prep_cvt<<<grid, 128>>>(query, kv, fnorm_w, cnorm_w,
                                f_Win, c_Win, f_Wout, c_Wout, outp_w);
    }

    // (1) in_proj GEMMs
    {
        dim3 grid(ZXW / 128, (BB * LL) / 128, 2);
        gemm_tf32<<<grid, 256, GEMM_SMEM>>>(u32_f, u32_c, win_f, win_c, zx_f, zx_c,
                                            nullptr, BB * LL, ZXW, DM, DM, ZXW, ZXW, 0);
    }

    // (2) conv+silu + dt/la (fused)
    {
        dim3 grid(BB * LL + (BB * LL) / 16, 2);
        conv_dt<<<grid, 288>>>(f_convw, f_convb, c_convw, c_convb,
                               f_Win, c_Win, f_dtb, c_dtb, f_Alog, c_Alog);
    }

    // (3) chunked SSD phase A: chunk states
    chunk_state<<<NCHH, 128>>>();

    // (4) phase B: inter-chunk state scan
    state_scan<<<2 * BB * NH, 1024>>>();

    // (5) phase C: chunk outputs (128 threads, causal skip)
    chunk_out<<<NCHH, 128, CO_SMEM>>>(f_D, c_D);

    // (6) gate + rmsnorm
    yz_norm<<<2 * BB * LQ, 256>>>(f_normw, c_normw);

    // (7) out-projection GEMMs
    {
        dim3 grid(DM / 128, (BB * LQ) / 128, 2);
        gemm_tf32<<<grid, 256, GEMM_SMEM>>>(nrm_f, nrm_c, wout_f, wout_c,
                                            fsP, out + BB * LQ * DM,
                                            nullptr, BB * LQ, DM, DIN, DIN, DM, DM, 1);
    }

    // (8) factual final projection with bias
    {
        dim3 grid(DM / 128, (BB * LQ) / 128, 1);
        gemm_tf32<<<grid, 256, GEMM_SMEM>>>(fsP, fsP, wo32P, wo32P, out, out,
                                            outp_b, BB * LQ, DM, DM, DM, DM, DM, 0);
    }
}